// round 3
// baseline (speedup 1.0000x reference)
#include <cuda_runtime.h>

// Problem dims (fixed by the dataset): B=64, C=3, H=W=512, fp32 NCHW.
#define HH 512
#define WW 512
#define CS (HH * WW)

#define TX 32
#define TY 16
#define HALO 3
#define RW (TX + 2 * HALO)   // 38
#define RH (TY + 2 * HALO)   // 22
#define RWP 40               // padded row stride for smem
#define NTHREADS (TX * TY)   // 512

// Gaussian weights for ks=7, sigma=2
#define W0 0.07015933f
#define W1 0.13107488f
#define W2 0.19071282f
#define W3 0.21610593f

__device__ __forceinline__ int reflect_idx(int i, int n) {
    // single reflection suffices for |halo| <= 3 << n
    if (i < 0) i = -i;
    else if (i >= n) i = 2 * n - 2 - i;
    return i;
}

__global__ __launch_bounds__(NTHREADS)
void hsv_adv_fused_kernel(const float* __restrict__ vars,
                          const float* __restrict__ img,
                          float* __restrict__ out)
{
    __shared__ float s_in[3][RH][RWP];
    __shared__ float s_tmp[3][TY][RWP];

    const int b  = blockIdx.z;
    const int x0 = blockIdx.x * TX;
    const int y0 = blockIdx.y * TY;
    const int tx = threadIdx.x;
    const int ty = threadIdx.y;
    const int tid = ty * TX + tx;

    const float* vb = vars + (size_t)b * 3 * CS;

    // ---- stage vars tile (with reflect halo) into smem, all 3 channels in one loop ----
    for (int i = tid; i < 3 * RH * RW; i += NTHREADS) {
        int c   = i / (RH * RW);
        int rem = i - c * (RH * RW);
        int r   = rem / RW;
        int col = rem - r * RW;
        int gy = reflect_idx(y0 + r - HALO, HH);
        int gx = reflect_idx(x0 + col - HALO, WW);
        s_in[c][r][col] = vb[(size_t)c * CS + gy * WW + gx];
    }
    __syncthreads();

    // ---- vertical 7-tap blur into s_tmp (covers full RW width) ----
    for (int i = tid; i < 3 * TY * RW; i += NTHREADS) {
        int c   = i / (TY * RW);
        int rem = i - c * (TY * RW);
        int r   = rem / RW;
        int col = rem - r * RW;
        float acc = W0 * (s_in[c][r    ][col] + s_in[c][r + 6][col])
                  + W1 * (s_in[c][r + 1][col] + s_in[c][r + 5][col])
                  + W2 * (s_in[c][r + 2][col] + s_in[c][r + 4][col])
                  + W3 *  s_in[c][r + 3][col];
        s_tmp[c][r][col] = acc;
    }
    __syncthreads();

    // ---- horizontal 7-tap blur for this thread's output pixel, 3 channels ----
    float vblur[3];
    #pragma unroll
    for (int c = 0; c < 3; ++c) {
        vblur[c] = W0 * (s_tmp[c][ty][tx    ] + s_tmp[c][ty][tx + 6])
                 + W1 * (s_tmp[c][ty][tx + 1] + s_tmp[c][ty][tx + 5])
                 + W2 * (s_tmp[c][ty][tx + 2] + s_tmp[c][ty][tx + 4])
                 + W3 *  s_tmp[c][ty][tx + 3];
    }

    const int gx = x0 + tx;
    const int gy = y0 + ty;
    const size_t base = (size_t)b * 3 * CS + (size_t)gy * WW + gx;

    // ---- rgb2hsv (matches jnp reference semantics exactly) ----
    const float r  = img[base];
    const float g  = img[base + CS];
    const float bl = img[base + 2 * CS];

    const float cmax = fmaxf(r, fmaxf(g, bl));
    const float cmin = fminf(r, fminf(g, bl));
    const float delta = cmax - cmin;
    const float ds = (delta == 0.0f) ? 1.0f : delta;

    float h;
    if (r >= g && r >= bl) {                 // argmax == 0 (first-index tie-break)
        h = fmodf((g - bl) / ds, 6.0f);
        if (h < 0.0f) h += 6.0f;             // Python/jnp mod: result has sign of divisor
    } else if (g >= bl) {                    // argmax == 1
        h = (bl - r) / ds + 2.0f;
    } else {                                 // argmax == 2
        h = (r - g) / ds + 4.0f;
    }
    if (delta == 0.0f) h = 0.0f;
    h *= (1.0f / 6.0f);

    float s = (cmax == 0.0f) ? 0.0f : delta / cmax;
    float v = cmax;

    // ---- add blurred adversarial noise, clip to [0,1] ----
    h = __saturatef(h + vblur[0]);
    s = __saturatef(s + vblur[1]);
    v = __saturatef(v + vblur[2]);

    // ---- hsv2rgb (matches jnp.select chain incl. idx==5/default) ----
    const float c  = v * s;
    const float hp = h * 6.0f;               // in [0, 6]
    const float xx = c * (1.0f - fabsf(fmodf(hp, 2.0f) - 1.0f));
    const float m  = v - c;
    int idx = ((int)floorf(hp)) % 6;         // 6 -> 0, matches floor(h*6) mod 6

    float rr, gg, bb;
    switch (idx) {
        case 0:  rr = c;    gg = xx;   bb = 0.0f; break;
        case 1:  rr = xx;   gg = c;    bb = 0.0f; break;
        case 2:  rr = 0.0f; gg = c;    bb = xx;   break;
        case 3:  rr = 0.0f; gg = xx;   bb = c;    break;
        case 4:  rr = xx;   gg = 0.0f; bb = c;    break;
        default: rr = c;    gg = 0.0f; bb = xx;   break;  // idx == 5 (reference default arm)
    }

    out[base]          = __saturatef(rr + m);
    out[base + CS]     = __saturatef(gg + m);
    out[base + 2 * CS] = __saturatef(bb + m);
}

extern "C" void kernel_launch(void* const* d_in, const int* in_sizes, int n_in,
                              void* d_out, int out_size)
{
    const float* vars = (const float*)d_in[0];
    const float* img  = (const float*)d_in[1];
    float* out        = (float*)d_out;

    const int B = in_sizes[0] / (3 * CS);   // 64 for the dataset shapes

    dim3 block(TX, TY, 1);
    dim3 grid(WW / TX, HH / TY, B);
    hsv_adv_fused_kernel<<<grid, block>>>(vars, img, out);
}

// round 4
// speedup vs baseline: 1.7080x; 1.7080x over previous
#include <cuda_runtime.h>

// B=64, C=3, H=W=512, fp32 NCHW.
#define HH 512
#define WW 512
#define CS (HH * WW)

#define TILE_W 128
#define TILE_H 8
#define NT 256               // 32 lanes x 8 warp-rows
#define RW 134               // TILE_W + 6
#define RWP 136              // padded smem row stride (float4-aligned)
#define RH 14                // TILE_H + 6

// Gaussian weights for ks=7, sigma=2
#define W0 0.07015933f
#define W1 0.13107488f
#define W2 0.19071282f
#define W3 0.21610593f

__device__ __forceinline__ int reflect_idx(int i, int n) {
    if (i < 0) i = -i;
    else if (i >= n) i = 2 * n - 2 - i;
    return i;
}

__device__ __forceinline__ void px_color(float r, float g, float bl,
                                         float dh, float dsn, float dv,
                                         float& orr, float& og, float& ob)
{
    const float cmax = fmaxf(r, fmaxf(g, bl));
    const float cmin = fminf(r, fminf(g, bl));
    const float delta = cmax - cmin;
    const float dsv = (delta == 0.0f) ? 1.0f : delta;

    float h;
    if (r >= g && r >= bl) {                 // argmax == 0 (first-index tie-break)
        h = fmodf((g - bl) / dsv, 6.0f);
        if (h < 0.0f) h += 6.0f;             // Python/jnp mod semantics
    } else if (g >= bl) {                    // argmax == 1
        h = (bl - r) / dsv + 2.0f;
    } else {                                 // argmax == 2
        h = (r - g) / dsv + 4.0f;
    }
    if (delta == 0.0f) h = 0.0f;
    h *= (1.0f / 6.0f);

    float s = (cmax == 0.0f) ? 0.0f : delta / cmax;
    float v = cmax;

    h = __saturatef(h + dh);
    s = __saturatef(s + dsn);
    v = __saturatef(v + dv);

    const float c  = v * s;
    const float hp = h * 6.0f;
    const float xx = c * (1.0f - fabsf(fmodf(hp, 2.0f) - 1.0f));
    const float m  = v - c;
    int idx = ((int)floorf(hp)) % 6;

    float rr, gg, bb;
    switch (idx) {
        case 0:  rr = c;    gg = xx;   bb = 0.0f; break;
        case 1:  rr = xx;   gg = c;    bb = 0.0f; break;
        case 2:  rr = 0.0f; gg = c;    bb = xx;   break;
        case 3:  rr = 0.0f; gg = xx;   bb = c;    break;
        case 4:  rr = xx;   gg = 0.0f; bb = c;    break;
        default: rr = c;    gg = 0.0f; bb = xx;   break;
    }
    orr = __saturatef(rr + m);
    og  = __saturatef(gg + m);
    ob  = __saturatef(bb + m);
}

__global__ __launch_bounds__(NT, 4)
void hsv_adv_fused_kernel(const float* __restrict__ vars,
                          const float* __restrict__ img,
                          float* __restrict__ out)
{
    __shared__ __align__(16) float s_in[3][RH][RWP];
    __shared__ __align__(16) float s_tmp[3][TILE_H][RWP];

    const int b    = blockIdx.z;
    const int x0   = blockIdx.x * TILE_W;
    const int y0   = blockIdx.y * TILE_H;
    const int tid  = threadIdx.x;
    const int lane = tid & 31;
    const int wrow = tid >> 5;           // 0..7 : this thread's output row

    // ---- prefetch images early (float4, fully coalesced) ----
    const int px = x0 + 4 * lane;
    const int py = y0 + wrow;
    const size_t ibase = (size_t)b * 3 * CS + (size_t)py * WW + px;
    const float4 ir = *(const float4*)(img + ibase);
    const float4 ig = *(const float4*)(img + ibase + CS);
    const float4 ib = *(const float4*)(img + ibase + 2 * CS);

    // ---- stage vars tile with reflect halo: warp-per-row, lane-strided cols ----
    const float* vb = vars + (size_t)b * 3 * CS;
    for (int rt = wrow; rt < 3 * RH; rt += 8) {
        const int c = rt / RH;           // constant-divisor, 2 instr
        const int r = rt - c * RH;
        const int gy = reflect_idx(y0 + r - 3, HH);
        const float* src = vb + (size_t)c * CS + gy * WW;
        #pragma unroll
        for (int k = 0; k < 5; ++k) {
            const int col = lane + k * 32;
            if (col < RW) {
                const int gx = reflect_idx(x0 + col - 3, WW);
                s_in[c][r][col] = src[gx];
            }
        }
    }
    __syncthreads();

    // ---- vertical 7-tap blur: one column per task, register sliding window ----
    #pragma unroll
    for (int pass = 0; pass < 2; ++pass) {
        const int task = pass * NT + tid;
        if (task < 3 * RW) {
            const int c = task / RW;
            const int j = task - c * RW;
            float v[RH];
            #pragma unroll
            for (int r = 0; r < RH; ++r) v[r] = s_in[c][r][j];
            #pragma unroll
            for (int r = 0; r < TILE_H; ++r) {
                s_tmp[c][r][j] = W0 * (v[r]     + v[r + 6])
                               + W1 * (v[r + 1] + v[r + 5])
                               + W2 * (v[r + 2] + v[r + 4])
                               + W3 *  v[r + 3];
            }
        }
    }
    __syncthreads();

    // ---- horizontal 7-tap blur: 3 aligned LDS.128 per channel, 4 outputs ----
    float blur[3][4];
    #pragma unroll
    for (int c = 0; c < 3; ++c) {
        const float4* rowp = (const float4*)&s_tmp[c][wrow][0];
        const float4 a  = rowp[lane];
        const float4 bq = rowp[lane + 1];
        const float4 cq = rowp[lane + 2];
        const float t[12] = { a.x,  a.y,  a.z,  a.w,
                              bq.x, bq.y, bq.z, bq.w,
                              cq.x, cq.y, cq.z, cq.w };
        #pragma unroll
        for (int q = 0; q < 4; ++q) {
            blur[c][q] = W0 * (t[q]     + t[q + 6])
                       + W1 * (t[q + 1] + t[q + 5])
                       + W2 * (t[q + 2] + t[q + 4])
                       + W3 *  t[q + 3];
        }
    }

    // ---- color math on 4 pixels, vectorized store ----
    float4 orv, ogv, obv;
    px_color(ir.x, ig.x, ib.x, blur[0][0], blur[1][0], blur[2][0], orv.x, ogv.x, obv.x);
    px_color(ir.y, ig.y, ib.y, blur[0][1], blur[1][1], blur[2][1], orv.y, ogv.y, obv.y);
    px_color(ir.z, ig.z, ib.z, blur[0][2], blur[1][2], blur[2][2], orv.z, ogv.z, obv.z);
    px_color(ir.w, ig.w, ib.w, blur[0][3], blur[1][3], blur[2][3], orv.w, ogv.w, obv.w);

    *(float4*)(out + ibase)          = orv;
    *(float4*)(out + ibase + CS)     = ogv;
    *(float4*)(out + ibase + 2 * CS) = obv;
}

extern "C" void kernel_launch(void* const* d_in, const int* in_sizes, int n_in,
                              void* d_out, int out_size)
{
    const float* vars = (const float*)d_in[0];
    const float* img  = (const float*)d_in[1];
    float* out        = (float*)d_out;

    const int B = in_sizes[0] / (3 * CS);

    dim3 block(NT, 1, 1);
    dim3 grid(WW / TILE_W, HH / TILE_H, B);
    hsv_adv_fused_kernel<<<grid, block>>>(vars, img, out);
}